// round 5
// baseline (speedup 1.0000x reference)
#include <cuda_runtime.h>
#include <cuda_bf16.h>

typedef unsigned long long ull;

// Weight table: g_wd[(ds1*3+ds2)*81 + dh1*27 + dw1*9 + dh2*3 + dw2] = (k, k, k', k')
__device__ float4 g_wd[729];

__device__ __forceinline__ ull pack2(float x, float y) {
    ull r; asm("mov.b64 %0, {%1, %2};" : "=l"(r) : "f"(x), "f"(y)); return r;
}
__device__ __forceinline__ ull fma2(ull a, ull b, ull c) {
    ull d; asm("fma.rn.f32x2 %0, %1, %2, %3;" : "=l"(d) : "l"(a), "l"(b), "l"(c)); return d;
}
__device__ __forceinline__ float2 unpack2(ull v) {
    float2 f; asm("mov.b64 {%0, %1}, %2;" : "=f"(f.x), "=f"(f.y) : "l"(v)); return f;
}

__global__ void prep_kernel(const float* __restrict__ kern) {
    int i = blockIdx.x * blockDim.x + threadIdx.x;
    if (i >= 729) return;
    int dw2 = i % 3, dh2 = (i/3)%3, dw1 = (i/9)%3, dh1 = (i/27)%3;
    int ds2 = (i/81)%3, ds1 = i/243;
    float k  = kern[((((ds1*3+ds2)*3+dh1)*3+dw1)*3+dh2)*3+dw2];
    float kt = kern[((((ds2*3+ds1)*3+dh2)*3+dw2)*3+dh1)*3+dw1];
    g_wd[i] = make_float4(k, k, kt, kt);
}

// ---------------------------------------------------------------------------
// Tile per block: (h1,w1,h2,w2) = (4,4,8,8), 256 threads, thread owns 4
// consecutive w2 as two packed pairs (p0,p1),(p2,p3) x 4 s_out x 2 kernels.
// Shared: 4 relu'd halo planes [6][6][10][12] (69120 B) + 729 x 16B weights
// (11664 B) = 80784 B -> 2 CTAs/SM.
// ---------------------------------------------------------------------------
#define PLANE_F   4320                 // 6*6*10*12 floats
#define SMEM_F    (4 * PLANE_F)        // 17280 floats
#define SMEM_BYTES (SMEM_F * 4 + 729 * 16)   // 69120 + 11664 = 80784

__global__ __launch_bounds__(256, 2)
void conv_kernel(const float* __restrict__ x, float* __restrict__ out) {
    extern __shared__ float sm[];
    const char* wds = (const char*)(sm + SMEM_F);

    const int tid = threadIdx.x;
    const int bid = blockIdx.x;
    const int bw2 = bid & 3;
    const int bh2 = (bid >> 2) & 3;
    const int bw1 = (bid >> 4) & 7;
    const int bh1 = bid >> 7;

    const int H1o = bh1 * 4 - 1, W1o = bw1 * 4 - 1;
    const int H2o = bh2 * 8 - 1, W2o = bw2 * 8 - 1;

    // ---- Load 4 halo planes (relu'd, zero-padded) + weight table ----
    for (int i = tid; i < 4 * 3600; i += 256) {
        int a4 = i % 10; int t = i / 10;
        int a3 = t % 10; t /= 10;
        int a2 = t % 6;  t /= 6;
        int a1 = t % 6;  int s = t / 6;
        int g1 = H1o + a1, g2 = W1o + a2, g3 = H2o + a3, g4 = W2o + a4;
        float v = 0.0f;
        if (((unsigned)g1 < 32u) && ((unsigned)g2 < 32u) &&
            ((unsigned)g3 < 32u) && ((unsigned)g4 < 32u)) {
            v = fmaxf(x[(((s * 32 + g1) * 32 + g2) * 32 + g3) * 32 + g4], 0.0f);
        }
        sm[s * PLANE_F + ((a1 * 6 + a2) * 10 + a3) * 12 + a4] = v;
    }
    {
        float4* wsm4 = (float4*)(sm + SMEM_F);
        for (int i = tid; i < 729; i += 256) wsm4[i] = g_wd[i];
    }
    __syncthreads();

    // ---- Thread -> output coords ----
    const int w2b = (tid & 1) * 4;       // owns w2b..w2b+3
    const int h2  = (tid >> 1) & 7;
    const int w1  = (tid >> 4) & 3;
    const int h1  = tid >> 6;
    const int trow = ((h1 * 6 + w1) * 10 + h2) * 12 + w2b;

    // Accumulators: pairs (p0,p1),(p2,p3) x 4 s_out x {k, k'}
    ull ak01[4], at01[4], ak23[4], at23[4];
#pragma unroll
    for (int so = 0; so < 4; so++) { ak01[so]=0; at01[so]=0; ak23[so]=0; at23[so]=0; }

#pragma unroll 1
    for (int s_in = 0; s_in < 4; s_in++) {
        const float* base = sm + s_in * PLANE_F + trow;
        const int s1i = s_in >> 1, s2i = s_in & 1;
        int wo[4];
#pragma unroll
        for (int so = 0; so < 4; so++) {
            int ds1 = s1i - (so >> 1) + 1;
            int ds2 = s2i - (so & 1) + 1;
            wo[so] = (ds1 * 3 + ds2) * 1296;          // ds block, bytes (81*16)
        }
#pragma unroll 1
        for (int dh1 = 0; dh1 < 3; dh1++) {
#pragma unroll
            for (int dw1 = 0; dw1 < 3; dw1++) {
#pragma unroll
                for (int dh2 = 0; dh2 < 3; dh2++) {
                    const float* row = base + dh1 * 720 + dw1 * 120 + dh2 * 12;
                    float4 v4 = *(const float4*)row;          // x0..x3
                    float2 v2 = *(const float2*)(row + 4);    // x4,x5
                    ull P01 = pack2(v4.x, v4.y);
                    ull P23 = pack2(v4.z, v4.w);
                    ull P45 = pack2(v2.x, v2.y);
                    ull P12 = pack2(v4.y, v4.z);
                    ull P34 = pack2(v4.w, v2.x);
                    const int tapo = dh1 * 432 + dw1 * 144 + dh2 * 48;
#pragma unroll
                    for (int so = 0; so < 4; so++) {
                        const ulonglong2* w =
                            (const ulonglong2*)(wds + (wo[so] + tapo));
                        ulonglong2 w0 = w[0];   // dw2=0: (k,k),(k',k')
                        ulonglong2 w1 = w[1];   // dw2=1
                        ulonglong2 w2 = w[2];   // dw2=2
                        ak01[so] = fma2(P01, w0.x, ak01[so]);
                        at01[so] = fma2(P01, w0.y, at01[so]);
                        ak23[so] = fma2(P23, w0.x, ak23[so]);
                        at23[so] = fma2(P23, w0.y, at23[so]);
                        ak01[so] = fma2(P12, w1.x, ak01[so]);
                        at01[so] = fma2(P12, w1.y, at01[so]);
                        ak23[so] = fma2(P34, w1.x, ak23[so]);
                        at23[so] = fma2(P34, w1.y, at23[so]);
                        ak01[so] = fma2(P23, w2.x, ak01[so]);
                        at01[so] = fma2(P23, w2.y, at01[so]);
                        ak23[so] = fma2(P45, w2.x, ak23[so]);
                        at23[so] = fma2(P45, w2.y, at23[so]);
                    }
                }
            }
        }
    }

    // ---- Epilogue: sigmoid both branches, mask by (x != 0), sum over s_out ----
    const int H1 = bh1 * 4 + h1, W1 = bw1 * 4 + w1;
    const int H2 = bh2 * 8 + h2, W2 = bw2 * 8 + w2b;
    const int base_sp = ((H1 * 32 + W1) * 32 + H2) * 32 + W2;

    float r0 = 0.f, r1 = 0.f, r2 = 0.f, r3 = 0.f;
#pragma unroll
    for (int so = 0; so < 4; so++) {
        float4 xs = *(const float4*)(x + so * 1048576 + base_sp);
        float2 k01 = unpack2(ak01[so]);
        float2 t01 = unpack2(at01[so]);
        float2 k23 = unpack2(ak23[so]);
        float2 t23 = unpack2(at23[so]);
        float s0 = 1.0f/(1.0f+__expf(-k01.x)) + 1.0f/(1.0f+__expf(-t01.x));
        float s1 = 1.0f/(1.0f+__expf(-k01.y)) + 1.0f/(1.0f+__expf(-t01.y));
        float s2 = 1.0f/(1.0f+__expf(-k23.x)) + 1.0f/(1.0f+__expf(-t23.x));
        float s3 = 1.0f/(1.0f+__expf(-k23.y)) + 1.0f/(1.0f+__expf(-t23.y));
        r0 += (xs.x != 0.0f) ? s0 : 0.0f;
        r1 += (xs.y != 0.0f) ? s1 : 0.0f;
        r2 += (xs.z != 0.0f) ? s2 : 0.0f;
        r3 += (xs.w != 0.0f) ? s3 : 0.0f;
    }
    *(float4*)(out + base_sp) = make_float4(r0, r1, r2, r3);
}

extern "C" void kernel_launch(void* const* d_in, const int* in_sizes, int n_in,
                              void* d_out, int out_size) {
    const float* x    = (const float*)d_in[0];   // (1,2,2,32,32,32,32)
    const float* kern = (const float*)d_in[1];   // (729,)
    float* out = (float*)d_out;                  // (1,32,32,32,32)

    prep_kernel<<<3, 256>>>(kern);

    cudaFuncSetAttribute(conv_kernel,
                         cudaFuncAttributeMaxDynamicSharedMemorySize, SMEM_BYTES);
    conv_kernel<<<1024, 256, SMEM_BYTES>>>(x, out);
}

// round 6
// speedup vs baseline: 1.2249x; 1.2249x over previous
#include <cuda_runtime.h>
#include <cuda_bf16.h>

typedef unsigned long long ull;

// Compressed weight pairs: g_wp[(ds1*3+ds2)*81 + (dh1*9+dw1*3+dh2)*3 + dw2] = (k, k')
__device__ ull g_wp[729];

__device__ __forceinline__ ull pack2(float x, float y) {
    ull r; asm("mov.b64 %0, {%1, %2};" : "=l"(r) : "f"(x), "f"(y)); return r;
}
__device__ __forceinline__ ull fma2(ull a, ull b, ull c) {
    ull d; asm("fma.rn.f32x2 %0, %1, %2, %3;" : "=l"(d) : "l"(a), "l"(b), "l"(c)); return d;
}
__device__ __forceinline__ float2 unpack2(ull v) {
    float2 f; asm("mov.b64 {%0, %1}, %2;" : "=f"(f.x), "=f"(f.y) : "l"(v)); return f;
}

__global__ void prep_kernel(const float* __restrict__ kern) {
    int i = blockIdx.x * blockDim.x + threadIdx.x;
    if (i >= 729) return;
    int dw2 = i % 3, dh2 = (i/3)%3, dw1 = (i/9)%3, dh1 = (i/27)%3;
    int ds2 = (i/81)%3, ds1 = i/243;
    float k  = kern[((((ds1*3+ds2)*3+dh1)*3+dw1)*3+dh2)*3+dw2];
    float kt = kern[((((ds2*3+ds1)*3+dh2)*3+dw2)*3+dh1)*3+dw1];
    g_wp[i] = pack2(k, kt);
}

// ---------------------------------------------------------------------------
// R1 instruction stream + compressed table + 3 CTAs/SM.
// Tile per block: (h1,w1,h2,w2) = (4,4,8,8) = 1024 points, 256 threads,
// each thread computes 4 consecutive w2 points x 4 s_out x 2 kernels.
// Shared: 4 relu'd halo planes [6][6][10][12] (69120 B) + 729 weight pairs
// (5832 B) = 74952 B <= 76032 -> 3 CTAs/SM.
// Weight addressing: 4 per-s_in hoisted pointers; all loads in the unrolled
// body use compile-time immediate offsets (no IMAD on the fma pipe).
// ---------------------------------------------------------------------------
#define PLANE_F   4320                 // 6*6*10*12 floats
#define SMEM_F    (4 * PLANE_F)        // 17280 floats
#define SMEM_BYTES (SMEM_F * 4 + 729 * 8)   // 69120 + 5832 = 74952

__global__ __launch_bounds__(256, 3)
void conv_kernel(const float* __restrict__ x, float* __restrict__ out) {
    extern __shared__ float sm[];
    ull* ws = (ull*)(sm + SMEM_F);

    const int tid = threadIdx.x;
    const int bid = blockIdx.x;
    const int bw2 = bid & 3;
    const int bh2 = (bid >> 2) & 3;
    const int bw1 = (bid >> 4) & 7;
    const int bh1 = bid >> 7;

    const int H1o = bh1 * 4 - 1, W1o = bw1 * 4 - 1;
    const int H2o = bh2 * 8 - 1, W2o = bw2 * 8 - 1;

    // ---- Load 4 halo planes (relu'd, zero-padded) + weight table ----
    for (int i = tid; i < 4 * 3600; i += 256) {
        int a4 = i % 10; int t = i / 10;
        int a3 = t % 10; t /= 10;
        int a2 = t % 6;  t /= 6;
        int a1 = t % 6;  int s = t / 6;
        int g1 = H1o + a1, g2 = W1o + a2, g3 = H2o + a3, g4 = W2o + a4;
        float v = 0.0f;
        if (((unsigned)g1 < 32u) && ((unsigned)g2 < 32u) &&
            ((unsigned)g3 < 32u) && ((unsigned)g4 < 32u)) {
            v = fmaxf(x[(((s * 32 + g1) * 32 + g2) * 32 + g3) * 32 + g4], 0.0f);
        }
        sm[s * PLANE_F + ((a1 * 6 + a2) * 10 + a3) * 12 + a4] = v;
    }
    for (int i = tid; i < 729; i += 256) ws[i] = g_wp[i];
    __syncthreads();

    // ---- Thread -> output coords ----
    const int w2b = (tid & 1) * 4;       // owns w2b..w2b+3
    const int h2  = (tid >> 1) & 7;
    const int w1  = (tid >> 4) & 3;
    const int h1  = tid >> 6;

    // acc[p][s_out] = (acc_k, acc_k') packed
    ull acc[4][4];
#pragma unroll
    for (int p = 0; p < 4; p++)
#pragma unroll
        for (int so = 0; so < 4; so++) acc[p][so] = 0ull;

#pragma unroll 1
    for (int s_in = 0; s_in < 4; s_in++) {
        const float* pl = sm + s_in * PLANE_F;
        const int s1i = s_in >> 1, s2i = s_in & 1;
        // 4 hoisted per-s_out weight base pointers (only integer math per s_in;
        // everything inside the unrolled body is immediate-offset).
        const ull* wp0 = ws + ((s1i + 1) * 3 + (s2i + 1)) * 81;   // so=0
        const ull* wp1 = ws + ((s1i + 1) * 3 +  s2i     ) * 81;   // so=1
        const ull* wp2 = ws + ( s1i      * 3 + (s2i + 1)) * 81;   // so=2
        const ull* wp3 = ws + ( s1i      * 3 +  s2i     ) * 81;   // so=3
#pragma unroll 1
        for (int dh1 = 0; dh1 < 3; dh1++) {
#pragma unroll
            for (int dw1 = 0; dw1 < 3; dw1++) {
#pragma unroll
                for (int dh2 = 0; dh2 < 3; dh2++) {
                    const float* row = pl +
                        (((h1 + dh1) * 6 + (w1 + dw1)) * 10 + (h2 + dh2)) * 12 + w2b;
                    // 6 contiguous, 16B-aligned input floats
                    float4 v4 = *(const float4*)row;
                    float2 v2 = *(const float2*)(row + 4);
                    ull xp[6];
                    xp[0] = pack2(v4.x, v4.x);
                    xp[1] = pack2(v4.y, v4.y);
                    xp[2] = pack2(v4.z, v4.z);
                    xp[3] = pack2(v4.w, v4.w);
                    xp[4] = pack2(v2.x, v2.x);
                    xp[5] = pack2(v2.y, v2.y);
                    const int goff = (dh1 * 9 + dw1 * 3 + dh2) * 3;  // immediate
#pragma unroll
                    for (int dw2 = 0; dw2 < 3; dw2++) {
                        ull w0 = wp0[goff + dw2];
                        ull w1 = wp1[goff + dw2];
                        ull w2 = wp2[goff + dw2];
                        ull w3 = wp3[goff + dw2];
#pragma unroll
                        for (int p = 0; p < 4; p++) {
                            acc[p][0] = fma2(xp[dw2 + p], w0, acc[p][0]);
                            acc[p][1] = fma2(xp[dw2 + p], w1, acc[p][1]);
                            acc[p][2] = fma2(xp[dw2 + p], w2, acc[p][2]);
                            acc[p][3] = fma2(xp[dw2 + p], w3, acc[p][3]);
                        }
                    }
                }
            }
        }
    }

    // ---- Epilogue: sigmoid both branches, mask by (x != 0), sum over s_out ----
    const int H1 = bh1 * 4 + h1, W1 = bw1 * 4 + w1;
    const int H2 = bh2 * 8 + h2, W2 = bw2 * 8 + w2b;
    const int base_sp = ((H1 * 32 + W1) * 32 + H2) * 32 + W2;

    float res[4];
#pragma unroll
    for (int p = 0; p < 4; p++) res[p] = 0.0f;

#pragma unroll
    for (int so = 0; so < 4; so++) {
        float4 xs = *(const float4*)(x + so * 1048576 + base_sp);
        float xv[4] = {xs.x, xs.y, xs.z, xs.w};
#pragma unroll
        for (int p = 0; p < 4; p++) {
            float2 a = unpack2(acc[p][so]);
            float s1 = 1.0f / (1.0f + __expf(-a.x));
            float s2 = 1.0f / (1.0f + __expf(-a.y));
            res[p] += (xv[p] != 0.0f) ? (s1 + s2) : 0.0f;
        }
    }
    *(float4*)(out + base_sp) = make_float4(res[0], res[1], res[2], res[3]);
}

extern "C" void kernel_launch(void* const* d_in, const int* in_sizes, int n_in,
                              void* d_out, int out_size) {
    const float* x    = (const float*)d_in[0];   // (1,2,2,32,32,32,32)
    const float* kern = (const float*)d_in[1];   // (729,)
    float* out = (float*)d_out;                  // (1,32,32,32,32)

    prep_kernel<<<3, 256>>>(kern);

    cudaFuncSetAttribute(conv_kernel,
                         cudaFuncAttributeMaxDynamicSharedMemorySize, SMEM_BYTES);
    conv_kernel<<<1024, 256, SMEM_BYTES>>>(x, out);
}